// round 12
// baseline (speedup 1.0000x reference)
#include <cuda_runtime.h>
#include <cstdint>

#define NN   50000      // N_NODES
#define EMAX 1700000    // max edges (spec: 1,600,000)

// ------------------------- device scratch (static, allowed) -----------------
__device__ __align__(16) float g_agg1[NN * 64];
__device__ __align__(16) float g_h1  [NN * 128];
__device__ __align__(16) float g_agg2[NN * 128];
__device__ __align__(16) float g_h2  [NN * 128];
__device__ int g_src [EMAX];
__device__ int g_dst [EMAX];
__device__ int g_deg [NN];
__device__ int g_fill[NN];
__device__ int g_rowptr[NN + 1];
__device__ int g_col [EMAX];

// ------------------------- decode edge_index (int32 OR int64) + zero ---------
// JAX reference declares int64, but default JAX config (x64 disabled) yields
// int32. Sniff dtype: int64 entries < 2^31 have zero high words; for int32
// random values in [0,50000) eight consecutive odd words are ~never all zero.
// Reading via the sniffed dtype keeps every access in bounds for BOTH cases
// (the long-long misread of an int32 buffer was the source of the 717 traps).
__global__ void decode_kernel(const void* __restrict__ eiraw, int E) {
    const unsigned* u = (const unsigned*)eiraw;
    bool w64 = true;
#pragma unroll
    for (int i = 0; i < 8; i++) w64 = w64 && (u[2 * i + 1] == 0u);
    int e = blockIdx.x * blockDim.x + threadIdx.x;
    if (e < E) {
        int s, t;
        if (w64) {
            const long long* p = (const long long*)eiraw;
            s = (int)p[e];  t = (int)p[E + e];
        } else {
            const int* p = (const int*)eiraw;
            s = p[e];       t = p[E + e];
        }
        g_src[e] = s;  g_dst[e] = t;
    }
    if (e < NN) { g_deg[e] = 0; g_fill[e] = 0; }
}

// ------------------------- degree histogram ----------------------------------
__global__ void hist_kernel(int E) {
    int e = blockIdx.x * blockDim.x + threadIdx.x;
    if (e < E) atomicAdd(&g_deg[g_dst[e]], 1);
}

// ------------------------- exclusive scan (single block, chunked) -------------
__global__ void scan_kernel() {
    __shared__ int smem[1024];
    int tid = threadIdx.x;
    int carry = 0;
    for (int base = 0; base < NN; base += 1024) {
        int idx = base + tid;
        int v = (idx < NN) ? g_deg[idx] : 0;
        smem[tid] = v;
        __syncthreads();
        for (int off = 1; off < 1024; off <<= 1) {
            int t = (tid >= off) ? smem[tid - off] : 0;
            __syncthreads();
            smem[tid] += t;
            __syncthreads();
        }
        if (idx < NN) g_rowptr[idx] = carry + smem[tid] - v;  // exclusive
        int total = smem[1023];
        __syncthreads();   // protect smem before next chunk overwrites
        carry += total;
    }
    if (tid == 0) g_rowptr[NN] = carry;
}

// ------------------------- CSR fill -------------------------------------------
__global__ void fill_kernel(int E) {
    int e = blockIdx.x * blockDim.x + threadIdx.x;
    if (e >= E) return;
    int t = g_dst[e];
    int pos = g_rowptr[t] + atomicAdd(&g_fill[t], 1);
    g_col[pos] = g_src[e];
}

// ------------------------- gather-aggregate, layer 1 (d=64) -------------------
// One warp per node; lane holds float2 (32*2 = 64 features). No atomics.
__global__ void agg1_kernel(const float* __restrict__ x) {
    int w = (blockIdx.x * blockDim.x + threadIdx.x) >> 5;
    int lane = threadIdx.x & 31;
    if (w >= NN) return;
    int beg = g_rowptr[w], end = g_rowptr[w + 1];
    float ax = 0.f, ay = 0.f;
    for (int j = beg; j < end; j++) {
        int s = g_col[j];                       // uniform broadcast load
        float2 v = ((const float2*)(x + (size_t)s * 64))[lane];
        ax += v.x; ay += v.y;
    }
    float inv = 1.0f / (float)max(end - beg, 1);
    float2 r; r.x = ax * inv; r.y = ay * inv;
    ((float2*)(g_agg1 + (size_t)w * 64))[lane] = r;
}

// ------------------------- gather-aggregate, layer 2 (d=128) ------------------
// One warp per node; lane holds float4 (32*4 = 128 features). No atomics.
__global__ void agg2_kernel() {
    int w = (blockIdx.x * blockDim.x + threadIdx.x) >> 5;
    int lane = threadIdx.x & 31;
    if (w >= NN) return;
    int beg = g_rowptr[w], end = g_rowptr[w + 1];
    float a0 = 0.f, a1 = 0.f, a2 = 0.f, a3 = 0.f;
    for (int j = beg; j < end; j++) {
        int s = g_col[j];
        float4 v = ((const float4*)(g_h1 + (size_t)s * 128))[lane];
        a0 += v.x; a1 += v.y; a2 += v.z; a3 += v.w;
    }
    float inv = 1.0f / (float)max(end - beg, 1);
    float4 r; r.x = a0 * inv; r.y = a1 * inv; r.z = a2 * inv; r.w = a3 * inv;
    ((float4*)(g_agg2 + (size_t)w * 128))[lane] = r;
}

// ------------------------- fused concat-GEMM + bias (+ReLU) ------------------
// C[node, n] = act( sum_k<K1 A1[node,k]*W1[k,n] + sum_k<K2 A2[node,k]*W2[k,n]
//                   + bias[n] )         (A1 is already mean-normalized)
// Block tile: 64 nodes x N cols. 256 threads. Per-thread 4 x (N/16) tile,
// column swizzle n = tx + 16*j.
template <int K1, int K2, int N, bool RELU>
__device__ __forceinline__ void gemm_body(const float* __restrict__ A1,
                                          const float* __restrict__ A2,
                                          const float* __restrict__ W1,
                                          const float* __restrict__ W2,
                                          const float* __restrict__ bias,
                                          float* __restrict__ C) {
    constexpr int K  = K1 + K2;
    constexpr int KT = 16;
    constexpr int TN = N / 16;

    __shared__ float As[KT][64 + 1];   // +1 pad: conflict-free transposed store
    __shared__ float Ws[KT][N];

    const int tid = threadIdx.x;
    const int tx  = tid & 15;          // column group
    const int ty  = tid >> 4;          // row group
    const int m0  = blockIdx.x * 64;

    float c[4][TN];
#pragma unroll
    for (int i = 0; i < 4; i++)
#pragma unroll
        for (int j = 0; j < TN; j++) c[i][j] = 0.f;

    for (int kt = 0; kt < K / KT; kt++) {
        // --- load A tile (64 x 16), transposed into As[k][m] ---
#pragma unroll
        for (int i = 0; i < 4; i++) {
            int idx = tid + i * 256;       // 0..1023
            int m   = idx >> 4;
            int kl  = idx & 15;
            int k   = kt * KT + kl;
            int node = m0 + m;
            float v = 0.f;
            if (node < NN) {
                if (K1 > 0 && k < K1) v = A1[(size_t)node * K1 + k];
                else                  v = A2[(size_t)node * K2 + (k - K1)];
            }
            As[kl][m] = v;
        }
        // --- load W tile (16 x N) ---
#pragma unroll
        for (int i = 0; i < KT * N / 256; i++) {
            int idx = tid + i * 256;
            int kl  = idx / N;
            int n   = idx - kl * N;
            int k   = kt * KT + kl;
            float w = (K1 > 0 && k < K1) ? W1[k * N + n] : W2[(k - K1) * N + n];
            Ws[kl][n] = w;
        }
        __syncthreads();

#pragma unroll
        for (int kk = 0; kk < KT; kk++) {
            float a[4];
#pragma unroll
            for (int i = 0; i < 4; i++) a[i] = As[kk][ty * 4 + i];
            float w[TN];
#pragma unroll
            for (int j = 0; j < TN; j++) w[j] = Ws[kk][tx + 16 * j];
#pragma unroll
            for (int i = 0; i < 4; i++)
#pragma unroll
                for (int j = 0; j < TN; j++) c[i][j] += a[i] * w[j];
        }
        __syncthreads();
    }

    // --- epilogue ---
#pragma unroll
    for (int i = 0; i < 4; i++) {
        int node = m0 + ty * 4 + i;
        if (node >= NN) continue;
#pragma unroll
        for (int j = 0; j < TN; j++) {
            int n = tx + 16 * j;
            float v = c[i][j] + bias[n];
            if (RELU) v = fmaxf(v, 0.f);
            C[(size_t)node * N + n] = v;
        }
    }
}

__global__ void __launch_bounds__(256)
gemm1_kernel(const float* __restrict__ x, const float* __restrict__ Wl,
             const float* __restrict__ Wr, const float* __restrict__ b) {
    gemm_body<64, 64, 128, true>(g_agg1, x, Wl, Wr, b, g_h1);
}

__global__ void __launch_bounds__(256)
gemm2_kernel(const float* __restrict__ Wl, const float* __restrict__ Wr,
             const float* __restrict__ b) {
    gemm_body<128, 128, 128, true>(g_agg2, g_h1, Wl, Wr, b, g_h2);
}

__global__ void __launch_bounds__(256)
gemm3_kernel(const float* __restrict__ W, const float* __restrict__ b,
             float* __restrict__ out) {
    gemm_body<0, 128, 64, false>(nullptr, g_h2, nullptr, W, b, out);
}

// ------------------------- launch -------------------------------------------
extern "C" void kernel_launch(void* const* d_in, const int* in_sizes, int n_in,
                              void* d_out, int out_size) {
    const float* x     = (const float*)d_in[0];
    const void*  ei    = d_in[1];            // int32 or int64 — decoded on device
    const float* W_l1  = (const float*)d_in[2];
    const float* b_l1  = (const float*)d_in[3];
    const float* W_r1  = (const float*)d_in[4];
    const float* W_l2  = (const float*)d_in[5];
    const float* b_l2  = (const float*)d_in[6];
    const float* W_r2  = (const float*)d_in[7];
    const float* W_out = (const float*)d_in[8];
    const float* b_out = (const float*)d_in[9];
    float*       out   = (float*)d_out;

    const int E = in_sizes[1] / 2;           // element count / 2 = edges

    // --- decode indices (dtype-robust) + zero deg/fill ---
    decode_kernel<<<(E + 255) / 256, 256>>>(ei, E);

    // --- CSR build (int atomics only) ---
    hist_kernel<<<(E + 255) / 256, 256>>>(E);
    scan_kernel<<<1, 1024>>>();
    fill_kernel<<<(E + 255) / 256, 256>>>(E);

    // --- layer 1 ---
    agg1_kernel<<<(NN * 32 + 255) / 256, 256>>>(x);
    gemm1_kernel<<<(NN + 63) / 64, 256>>>(x, W_l1, W_r1, b_l1);

    // --- layer 2 ---
    agg2_kernel<<<(NN * 32 + 255) / 256, 256>>>();
    gemm2_kernel<<<(NN + 63) / 64, 256>>>(W_l2, W_r2, b_l2);

    // --- output layer ---
    gemm3_kernel<<<(NN + 63) / 64, 256>>>(W_out, b_out, out);
}